// round 1
// baseline (speedup 1.0000x reference)
#include <cuda_runtime.h>
#include <math.h>

#define N_TOT 262144
#define E_DIM 512
#define H_DIM 256
#define B_BAGS 512

// Scratch (allocation-free rule: __device__ globals)
__device__ float g_alpha[N_TOT];          // unnormalized exp scores
__device__ float g_sum_alpha[B_BAGS];     // per-bag softmax denominators
__device__ float g_bag_sum[B_BAGS * E_DIM]; // per-bag weighted (unnormalized) sums

// ---------------------------------------------------------------------------
// K0: zero the per-bag accumulators (graph replays need this every launch)
// ---------------------------------------------------------------------------
__global__ void k0_zero() {
    int i = blockIdx.x * blockDim.x + threadIdx.x;
    if (i < B_BAGS * E_DIM) g_bag_sum[i] = 0.0f;
    if (i < B_BAGS) g_sum_alpha[i] = 0.0f;
}

// ---------------------------------------------------------------------------
// K1: fused  v = tanh(x @ Vw^T + Vb);  s = v @ ww^T + wb;  alpha = exp(s)
// Block tile: 64 rows (M) x 256 cols (full H). 256 threads (tx 0..31, ty 0..7).
// Per-thread microtile: 8 M x 8 H (rows ty*8+i, cols tx+32*j).
// K-chunks of 16 through shared memory.
// ---------------------------------------------------------------------------
__global__ __launch_bounds__(256, 2)
void k1_score(const float* __restrict__ x,    // [N, E]
              const float* __restrict__ Vw,   // [H, E]
              const float* __restrict__ Vb,   // [H]
              const float* __restrict__ ww,   // [1, H]
              const float* __restrict__ wb,   // [1]
              const int*   __restrict__ bidx) // [N]
{
    __shared__ float sx[16][65];    // sx[k][m] = x[r0+m][e0+k]  (padded)
    __shared__ float sw[16][256];   // sw[k][h] = Vw[h][e0+k]

    const int t  = threadIdx.x;
    const int tx = t & 31;
    const int ty = t >> 5;
    const int r0 = blockIdx.x * 64;

    float acc[8][8];
#pragma unroll
    for (int i = 0; i < 8; i++)
#pragma unroll
        for (int j = 0; j < 8; j++) acc[i][j] = 0.0f;

    const int mload = t >> 2;   // 0..63: row within tile this thread loads
    const int quad  = t & 3;    // which float4 of the 16-wide K chunk

    for (int e0 = 0; e0 < E_DIM; e0 += 16) {
        // load x tile (64 rows x 16 k), transposed into sx[k][m]
        float4 xa = *(const float4*)(x + (size_t)(r0 + mload) * E_DIM + e0 + quad * 4);
        sx[quad * 4 + 0][mload] = xa.x;
        sx[quad * 4 + 1][mload] = xa.y;
        sx[quad * 4 + 2][mload] = xa.z;
        sx[quad * 4 + 3][mload] = xa.w;

        // load Vw tile: thread t owns h = t, reads 16 contiguous k
        const float* wrow = Vw + (size_t)t * E_DIM + e0;
        float4 w0 = *(const float4*)(wrow + 0);
        float4 w1 = *(const float4*)(wrow + 4);
        float4 w2 = *(const float4*)(wrow + 8);
        float4 w3 = *(const float4*)(wrow + 12);
        sw[0][t]  = w0.x; sw[1][t]  = w0.y; sw[2][t]  = w0.z; sw[3][t]  = w0.w;
        sw[4][t]  = w1.x; sw[5][t]  = w1.y; sw[6][t]  = w1.z; sw[7][t]  = w1.w;
        sw[8][t]  = w2.x; sw[9][t]  = w2.y; sw[10][t] = w2.z; sw[11][t] = w2.w;
        sw[12][t] = w3.x; sw[13][t] = w3.y; sw[14][t] = w3.z; sw[15][t] = w3.w;

        __syncthreads();

#pragma unroll
        for (int k = 0; k < 16; k++) {
            float a[8], w[8];
#pragma unroll
            for (int i = 0; i < 8; i++) a[i] = sx[k][ty * 8 + i];   // warp-broadcast
#pragma unroll
            for (int j = 0; j < 8; j++) w[j] = sw[k][tx + 32 * j];  // conflict-free
#pragma unroll
            for (int i = 0; i < 8; i++)
#pragma unroll
                for (int j = 0; j < 8; j++)
                    acc[i][j] = fmaf(a[i], w[j], acc[i][j]);
        }
        __syncthreads();
    }

    // epilogue: tanh, dot with ww over H (8 local + warp-reduce over tx), exp
    float vb[8], wv[8];
#pragma unroll
    for (int j = 0; j < 8; j++) {
        int h = tx + 32 * j;
        vb[j] = Vb[h];
        wv[j] = ww[h];
    }
    const float wbias = wb[0];

#pragma unroll
    for (int i = 0; i < 8; i++) {
        float s = 0.0f;
#pragma unroll
        for (int j = 0; j < 8; j++)
            s += tanhf(acc[i][j] + vb[j]) * wv[j];
        // warp reduction across the 32 tx lanes (full H)
#pragma unroll
        for (int off = 16; off > 0; off >>= 1)
            s += __shfl_xor_sync(0xFFFFFFFFu, s, off);
        if (tx == 0) {
            int r = r0 + ty * 8 + i;
            float al = expf(s + wbias);
            g_alpha[r] = al;
            atomicAdd(&g_sum_alpha[bidx[r]], al);
        }
    }
}

// ---------------------------------------------------------------------------
// K2: bag_sum[b][:] += alpha[n] * x[n][:]   (unnormalized; indices sorted)
// 128 threads: thread owns 4 consecutive e (one float4 column group).
// Block handles 128 consecutive rows; run-length accumulate in registers,
// flush with atomicAdd at bag boundaries.
// ---------------------------------------------------------------------------
__global__ __launch_bounds__(128)
void k2_pool(const float* __restrict__ x, const int* __restrict__ bidx)
{
    const int r0 = blockIdx.x * 128;
    const int e4 = threadIdx.x;             // float4 index 0..127
    const float4* xp = (const float4*)x;

    float4 acc = make_float4(0.f, 0.f, 0.f, 0.f);
    int cur = bidx[r0];

#pragma unroll 4
    for (int r = r0; r < r0 + 128; r++) {
        int b = bidx[r];
        if (b != cur) {
            float* dst = &g_bag_sum[(size_t)cur * E_DIM + e4 * 4];
            atomicAdd(dst + 0, acc.x);
            atomicAdd(dst + 1, acc.y);
            atomicAdd(dst + 2, acc.z);
            atomicAdd(dst + 3, acc.w);
            acc = make_float4(0.f, 0.f, 0.f, 0.f);
            cur = b;
        }
        float al = g_alpha[r];
        float4 xv = xp[(size_t)r * (E_DIM / 4) + e4];
        acc.x = fmaf(al, xv.x, acc.x);
        acc.y = fmaf(al, xv.y, acc.y);
        acc.z = fmaf(al, xv.z, acc.z);
        acc.w = fmaf(al, xv.w, acc.w);
    }
    float* dst = &g_bag_sum[(size_t)cur * E_DIM + e4 * 4];
    atomicAdd(dst + 0, acc.x);
    atomicAdd(dst + 1, acc.y);
    atomicAdd(dst + 2, acc.z);
    atomicAdd(dst + 3, acc.w);
}

// ---------------------------------------------------------------------------
// K3: logits[b][c] = (bag_sum[b]·dw[c]) / sum_alpha[b] + db[c]; 2-way softmax
// One warp per bag.
// ---------------------------------------------------------------------------
__global__ __launch_bounds__(256)
void k3_logits(const float* __restrict__ dw,  // [2, E]
               const float* __restrict__ db,  // [2]
               float* __restrict__ out)       // [B, 2]
{
    int warp = (blockIdx.x * blockDim.x + threadIdx.x) >> 5;
    int lane = threadIdx.x & 31;
    if (warp >= B_BAGS) return;

    float s0 = 0.0f, s1 = 0.0f;
    for (int e = lane; e < E_DIM; e += 32) {
        float bs = g_bag_sum[(size_t)warp * E_DIM + e];
        s0 = fmaf(bs, dw[e], s0);
        s1 = fmaf(bs, dw[E_DIM + e], s1);
    }
#pragma unroll
    for (int off = 16; off > 0; off >>= 1) {
        s0 += __shfl_xor_sync(0xFFFFFFFFu, s0, off);
        s1 += __shfl_xor_sync(0xFFFFFFFFu, s1, off);
    }
    if (lane == 0) {
        float inv = 1.0f / g_sum_alpha[warp];
        float l0 = fmaf(s0, inv, db[0]);
        float l1 = fmaf(s1, inv, db[1]);
        float m = fmaxf(l0, l1);
        float e0 = expf(l0 - m), e1 = expf(l1 - m);
        float d = e0 + e1;
        out[warp * 2 + 0] = e0 / d;
        out[warp * 2 + 1] = e1 / d;
    }
}

// ---------------------------------------------------------------------------
extern "C" void kernel_launch(void* const* d_in, const int* in_sizes, int n_in,
                              void* d_out, int out_size)
{
    const float* x    = (const float*)d_in[0]; // bag_encoding [N, E]
    const float* Vw   = (const float*)d_in[1]; // [H, E]
    const float* Vb   = (const float*)d_in[2]; // [H]
    const float* ww   = (const float*)d_in[3]; // [1, H]
    const float* wb   = (const float*)d_in[4]; // [1]
    const float* dw   = (const float*)d_in[5]; // [2, E]
    const float* db   = (const float*)d_in[6]; // [2]
    const int*   bidx = (const int*)d_in[7];   // [N]
    float* out = (float*)d_out;                // [B, 2]

    k0_zero<<<(B_BAGS * E_DIM + 255) / 256, 256>>>();
    k1_score<<<N_TOT / 64, 256>>>(x, Vw, Vb, ww, wb, bidx);
    k2_pool<<<N_TOT / 128, 128>>>(x, bidx);
    k3_logits<<<(B_BAGS * 32 + 255) / 256, 256>>>(dw, db, out);
}

// round 3
// speedup vs baseline: 3.2746x; 3.2746x over previous
#include <cuda_runtime.h>
#include <cstdint>
#include <math.h>

#define N_TOT 262144
#define E_DIM 512
#define H_DIM 256
#define B_BAGS 512

// Scratch (allocation-free rule: __device__ globals)
__device__ float g_alpha[N_TOT];
__device__ float g_sum_alpha[B_BAGS];
__device__ float g_bag_sum[B_BAGS * E_DIM];

// ============================================================================
// helpers
// ============================================================================
__device__ __forceinline__ uint32_t smem_to_u32(const void* p) {
    uint32_t a;
    asm("{ .reg .u64 t; cvta.to.shared.u64 t, %1; cvt.u32.u64 %0, t; }" : "=r"(a) : "l"(p));
    return a;
}
#define CP_ASYNC16(dst_u32, src_ptr) \
    asm volatile("cp.async.cg.shared.global [%0], [%1], 16;" :: "r"(dst_u32), "l"(src_ptr))
#define CP_COMMIT() asm volatile("cp.async.commit_group;" ::: "memory")
#define CP_WAIT(n)  asm volatile("cp.async.wait_group %0;" :: "n"(n) : "memory")

// mma.sync m16n8k8 tf32: D = A@B + C (fp32 accum). A row-major, B col-major.
__device__ __forceinline__ void mma_tf32(float* c, const uint32_t* a, const uint32_t* b) {
    asm volatile(
        "mma.sync.aligned.m16n8k8.row.col.f32.tf32.tf32.f32 "
        "{%0,%1,%2,%3}, {%4,%5,%6,%7}, {%8,%9}, {%0,%1,%2,%3};"
        : "+f"(c[0]), "+f"(c[1]), "+f"(c[2]), "+f"(c[3])
        : "r"(a[0]), "r"(a[1]), "r"(a[2]), "r"(a[3]), "r"(b[0]), "r"(b[1]));
}

// ============================================================================
// K1 geometry: CTA = 128(M) x 256(H) x K512, k-chunk 32, double buffered.
// 16 warps: warp_m = wid>>3 (64 rows), warp_n = wid&7 (32 H cols).
// smem rows padded to 36 floats (4q+r bank-perfect fragment loads).
// ============================================================================
#define KC 32
#define STAGES (E_DIM / KC)          // 16
#define A_ROW_F 36
#define B_ROW_F 36
#define A_BUF_B (128 * A_ROW_F * 4)  // 18432
#define B_BUF_B (256 * B_ROW_F * 4)  // 36864
#define SM_A0 0
#define SM_A1 (A_BUF_B)
#define SM_B0 (2 * A_BUF_B)
#define SM_B1 (2 * A_BUF_B + B_BUF_B)
#define SM_TOTAL (2 * A_BUF_B + 2 * B_BUF_B)   // 110592

__global__ void k0_zero() {
    int i = blockIdx.x * blockDim.x + threadIdx.x;
    if (i < B_BAGS * E_DIM) g_bag_sum[i] = 0.0f;
    if (i < B_BAGS) g_sum_alpha[i] = 0.0f;
}

__device__ __forceinline__ void k1_issue_stage(uint32_t smem_base, int buf, int s,
                                               const float4* x4, const float4* w4,
                                               int r0, int t) {
    const uint32_t abase = smem_base + (buf ? SM_A1 : SM_A0);
    const uint32_t bbase = smem_base + (buf ? SM_B1 : SM_B0);
    const int c0 = s * 8;  // float4 column base within row (8 float4 = 32 floats)
    // A: 128 rows x 8 float4 = 1024 -> 2 per thread
#pragma unroll
    for (int i = 0; i < 2; i++) {
        int id = t + i * 512, row = id >> 3, c4 = id & 7;
        CP_ASYNC16(abase + (uint32_t)(row * (A_ROW_F * 4) + c4 * 16),
                   (const void*)(x4 + (size_t)(r0 + row) * (E_DIM / 4) + c0 + c4));
    }
    // B: 256 rows x 8 float4 = 2048 -> 4 per thread
#pragma unroll
    for (int i = 0; i < 4; i++) {
        int id = t + i * 512, row = id >> 3, c4 = id & 7;
        CP_ASYNC16(bbase + (uint32_t)(row * (B_ROW_F * 4) + c4 * 16),
                   (const void*)(w4 + (size_t)row * (E_DIM / 4) + c0 + c4));
    }
    CP_COMMIT();
}

__global__ __launch_bounds__(512, 1)
void k1_score(const float* __restrict__ x,    // [N, E]
              const float* __restrict__ Vw,   // [H, E]
              const float* __restrict__ Vb,   // [H]
              const float* __restrict__ ww,   // [1, H]
              const float* __restrict__ wb,   // [1]
              const int*   __restrict__ bidx) // [N]
{
    extern __shared__ char smem[];
    const uint32_t smem_base = smem_to_u32(smem);
    const int t    = threadIdx.x;
    const int wid  = t >> 5;
    const int lane = t & 31;
    const int q    = lane >> 2;     // 0..7
    const int rr   = lane & 3;      // 0..3
    const int wm   = wid >> 3;      // 0..1 : rows [wm*64, +64)
    const int wn   = wid & 7;       // 0..7 : cols [wn*32, +32)
    const int r0   = blockIdx.x * 128;

    const float4* x4 = (const float4*)x;
    const float4* w4 = (const float4*)Vw;

    float acc[4][4][4];
#pragma unroll
    for (int mt = 0; mt < 4; mt++)
#pragma unroll
        for (int nt = 0; nt < 4; nt++)
#pragma unroll
            for (int j = 0; j < 4; j++) acc[mt][nt][j] = 0.0f;

    k1_issue_stage(smem_base, 0, 0, x4, w4, r0, t);

    const float* sAf[2] = {(const float*)(smem + SM_A0), (const float*)(smem + SM_A1)};
    const float* sBf[2] = {(const float*)(smem + SM_B0), (const float*)(smem + SM_B1)};

    for (int s = 0; s < STAGES; s++) {
        if (s + 1 < STAGES) {
            k1_issue_stage(smem_base, (s + 1) & 1, s + 1, x4, w4, r0, t);
            CP_WAIT(1);
        } else {
            CP_WAIT(0);
        }
        __syncthreads();

        const float* sA = sAf[s & 1];
        const float* sB = sBf[s & 1];
#pragma unroll
        for (int k8 = 0; k8 < 4; k8++) {
            const int kb = k8 * 8;
            uint32_t af[4][4], bf[4][2];
#pragma unroll
            for (int mt = 0; mt < 4; mt++) {
                const int br = wm * 64 + mt * 16;
                af[mt][0] = __float_as_uint(sA[(br + q) * A_ROW_F + kb + rr]);
                af[mt][1] = __float_as_uint(sA[(br + q + 8) * A_ROW_F + kb + rr]);
                af[mt][2] = __float_as_uint(sA[(br + q) * A_ROW_F + kb + rr + 4]);
                af[mt][3] = __float_as_uint(sA[(br + q + 8) * A_ROW_F + kb + rr + 4]);
            }
#pragma unroll
            for (int nt = 0; nt < 4; nt++) {
                const int bc = wn * 32 + nt * 8;
                bf[nt][0] = __float_as_uint(sB[(bc + q) * B_ROW_F + kb + rr]);
                bf[nt][1] = __float_as_uint(sB[(bc + q) * B_ROW_F + kb + rr + 4]);
            }
#pragma unroll
            for (int mt = 0; mt < 4; mt++)
#pragma unroll
                for (int nt = 0; nt < 4; nt++)
                    mma_tf32(acc[mt][nt], af[mt], bf[nt]);
        }
        __syncthreads();
    }

    // ---------------- epilogue ----------------
    // per-thread cols: c = wn*32 + nt*8 + 2*rr + j
    float vb[4][2], wv[4][2];
#pragma unroll
    for (int nt = 0; nt < 4; nt++)
#pragma unroll
        for (int j = 0; j < 2; j++) {
            int c = wn * 32 + nt * 8 + 2 * rr + j;
            vb[nt][j] = Vb[c];
            wv[nt][j] = ww[c];
        }

    float* s_red = (float*)smem;      // 128 floats, overlays A buf (loads all drained)
    if (t < 128) s_red[t] = 0.0f;
    __syncthreads();

#pragma unroll
    for (int mt = 0; mt < 4; mt++) {
        float plo = 0.0f, phi = 0.0f;
#pragma unroll
        for (int nt = 0; nt < 4; nt++)
#pragma unroll
            for (int j = 0; j < 2; j++) {
                float tlo, thi;
                asm("tanh.approx.f32 %0, %1;" : "=f"(tlo) : "f"(acc[mt][nt][j] + vb[nt][j]));
                asm("tanh.approx.f32 %0, %1;" : "=f"(thi) : "f"(acc[mt][nt][j + 2] + vb[nt][j]));
                plo = fmaf(tlo, wv[nt][j], plo);
                phi = fmaf(thi, wv[nt][j], phi);
            }
        // quad reduce across rr (4 lanes share a row)
        plo += __shfl_xor_sync(0xFFFFFFFFu, plo, 1);
        plo += __shfl_xor_sync(0xFFFFFFFFu, plo, 2);
        phi += __shfl_xor_sync(0xFFFFFFFFu, phi, 1);
        phi += __shfl_xor_sync(0xFFFFFFFFu, phi, 2);
        if (rr == 0) {
            int row = wm * 64 + mt * 16 + q;
            atomicAdd(&s_red[row], plo);
            atomicAdd(&s_red[row + 8], phi);
        }
    }
    __syncthreads();

    if (t < 128) {
        int r = r0 + t;
        float al = expf(s_red[t] + wb[0]);
        g_alpha[r] = al;
        atomicAdd(&g_sum_alpha[bidx[r]], al);
    }
}

// ---------------------------------------------------------------------------
// K2: bag_sum[b][:] += alpha[n] * x[n][:]  (sorted indices; run-length + atomics)
// ---------------------------------------------------------------------------
__global__ __launch_bounds__(128)
void k2_pool(const float* __restrict__ x, const int* __restrict__ bidx)
{
    const int r0 = blockIdx.x * 128;
    const int e4 = threadIdx.x;
    const float4* xp = (const float4*)x;

    float4 acc = make_float4(0.f, 0.f, 0.f, 0.f);
    int cur = bidx[r0];

#pragma unroll 4
    for (int r = r0; r < r0 + 128; r++) {
        int b = bidx[r];
        if (b != cur) {
            float* dst = &g_bag_sum[(size_t)cur * E_DIM + e4 * 4];
            atomicAdd(dst + 0, acc.x);
            atomicAdd(dst + 1, acc.y);
            atomicAdd(dst + 2, acc.z);
            atomicAdd(dst + 3, acc.w);
            acc = make_float4(0.f, 0.f, 0.f, 0.f);
            cur = b;
        }
        float al = g_alpha[r];
        float4 xv = xp[(size_t)r * (E_DIM / 4) + e4];
        acc.x = fmaf(al, xv.x, acc.x);
        acc.y = fmaf(al, xv.y, acc.y);
        acc.z = fmaf(al, xv.z, acc.z);
        acc.w = fmaf(al, xv.w, acc.w);
    }
    float* dst = &g_bag_sum[(size_t)cur * E_DIM + e4 * 4];
    atomicAdd(dst + 0, acc.x);
    atomicAdd(dst + 1, acc.y);
    atomicAdd(dst + 2, acc.z);
    atomicAdd(dst + 3, acc.w);
}

// ---------------------------------------------------------------------------
// K3: logits + 2-way softmax (one warp per bag), divide by sum_alpha here
// ---------------------------------------------------------------------------
__global__ __launch_bounds__(256)
void k3_logits(const float* __restrict__ dw, const float* __restrict__ db,
               float* __restrict__ out)
{
    int warp = (blockIdx.x * blockDim.x + threadIdx.x) >> 5;
    int lane = threadIdx.x & 31;
    if (warp >= B_BAGS) return;

    float s0 = 0.0f, s1 = 0.0f;
    for (int e = lane; e < E_DIM; e += 32) {
        float bs = g_bag_sum[(size_t)warp * E_DIM + e];
        s0 = fmaf(bs, dw[e], s0);
        s1 = fmaf(bs, dw[E_DIM + e], s1);
    }
#pragma unroll
    for (int off = 16; off > 0; off >>= 1) {
        s0 += __shfl_xor_sync(0xFFFFFFFFu, s0, off);
        s1 += __shfl_xor_sync(0xFFFFFFFFu, s1, off);
    }
    if (lane == 0) {
        float inv = 1.0f / g_sum_alpha[warp];
        float l0 = fmaf(s0, inv, db[0]);
        float l1 = fmaf(s1, inv, db[1]);
        float m = fmaxf(l0, l1);
        float e0 = expf(l0 - m), e1 = expf(l1 - m);
        float d = e0 + e1;
        out[warp * 2 + 0] = e0 / d;
        out[warp * 2 + 1] = e1 / d;
    }
}

// ---------------------------------------------------------------------------
extern "C" void kernel_launch(void* const* d_in, const int* in_sizes, int n_in,
                              void* d_out, int out_size)
{
    const float* x    = (const float*)d_in[0];
    const float* Vw   = (const float*)d_in[1];
    const float* Vb   = (const float*)d_in[2];
    const float* ww   = (const float*)d_in[3];
    const float* wb   = (const float*)d_in[4];
    const float* dw   = (const float*)d_in[5];
    const float* db   = (const float*)d_in[6];
    const int*   bidx = (const int*)d_in[7];
    float* out = (float*)d_out;

    static int smem_set = 0;
    if (!smem_set) {
        cudaFuncSetAttribute(k1_score, cudaFuncAttributeMaxDynamicSharedMemorySize, SM_TOTAL);
        smem_set = 1;
    }

    k0_zero<<<(B_BAGS * E_DIM + 255) / 256, 256>>>();
    k1_score<<<N_TOT / 128, 512, SM_TOTAL>>>(x, Vw, Vb, ww, wb, bidx);
    k2_pool<<<N_TOT / 128, 128>>>(x, bidx);
    k3_logits<<<(B_BAGS * 32 + 255) / 256, 256>>>(dw, db, out);
}

// round 5
// speedup vs baseline: 4.2373x; 1.2940x over previous
#include <cuda_runtime.h>
#include <cuda_fp16.h>
#include <cstdint>
#include <math.h>

#define N_TOT 262144
#define E_DIM 512
#define H_DIM 256
#define B_BAGS 512

// Scratch (allocation-free rule: __device__ globals)
__device__ float g_sum_alpha[B_BAGS];
__device__ float g_bag_sum[B_BAGS * E_DIM];

// ============================================================================
// helpers
// ============================================================================
__device__ __forceinline__ uint32_t smem_to_u32(const void* p) {
    uint32_t a;
    asm("{ .reg .u64 t; cvta.to.shared.u64 t, %1; cvt.u32.u64 %0, t; }" : "=r"(a) : "l"(p));
    return a;
}
#define LDM_X4(r0_, r1_, r2_, r3_, addr) \
    asm volatile("ldmatrix.sync.aligned.m8n8.x4.shared.b16 {%0,%1,%2,%3}, [%4];" \
                 : "=r"(r0_), "=r"(r1_), "=r"(r2_), "=r"(r3_) : "r"(addr))
#define STS128(addr, a, b, c, d) \
    asm volatile("st.shared.v4.b32 [%0], {%1,%2,%3,%4};" \
                 :: "r"(addr), "r"(a), "r"(b), "r"(c), "r"(d) : "memory")

__device__ __forceinline__ void mma_f16(float* c, const uint32_t* a, const uint32_t* b) {
    asm volatile(
        "mma.sync.aligned.m16n8k16.row.col.f32.f16.f16.f32 "
        "{%0,%1,%2,%3}, {%4,%5,%6,%7}, {%8,%9}, {%0,%1,%2,%3};"
        : "+f"(c[0]), "+f"(c[1]), "+f"(c[2]), "+f"(c[3])
        : "r"(a[0]), "r"(a[1]), "r"(a[2]), "r"(a[3]), "r"(b[0]), "r"(b[1]));
}
__device__ __forceinline__ uint32_t pack2(float lo, float hi) {
    __half2 h = __floats2half2_rn(lo, hi);
    return *reinterpret_cast<uint32_t*>(&h);
}

// ============================================================================
// K1 geometry: CTA = 128(M) x 256(H) x K512 fp16 mma, k-chunk 32.
// A tile fully resident (16 slices), B double buffered. 16 warps.
// Row stride 80B: 16B-aligned STS.128 AND conflict-free ldmatrix phases.
// ============================================================================
#define STAGES 16
#define AB_STRIDE 80
#define A_SLICE (128 * AB_STRIDE)        // 10240
#define SM_A 0
#define SM_B (STAGES * A_SLICE)          // 163840
#define B_BUF (256 * AB_STRIDE)          // 20480
#define SM_TOTAL (SM_B + 2 * B_BUF)      // 204800

__global__ void k0_zero() {
    int i = blockIdx.x * blockDim.x + threadIdx.x;
    if (i < B_BAGS * E_DIM) g_bag_sum[i] = 0.0f;
    if (i < B_BAGS) g_sum_alpha[i] = 0.0f;
}

__global__ __launch_bounds__(512, 1)
void k1_score(const float* __restrict__ x,    // [N, E]
              const float* __restrict__ Vw,   // [H, E]
              const float* __restrict__ Vb,   // [H]
              const float* __restrict__ ww,   // [1, H]
              const float* __restrict__ wb,   // [1]
              const int*   __restrict__ bidx) // [N]
{
    extern __shared__ char smem[];
    __shared__ float s_red[128];
    __shared__ float s_alpha[128];
    __shared__ int   s_bag[128];

    const uint32_t sb = smem_to_u32(smem);
    const int t    = threadIdx.x;
    const int wid  = t >> 5;
    const int lane = t & 31;
    const int q    = lane >> 2;
    const int rr   = lane & 3;
    const int wm   = wid >> 3;      // 0..1 : rows [wm*64, +64)
    const int wn   = wid & 7;       // 0..7 : cols [wn*32, +32)
    const int r0   = blockIdx.x * 128;

    const float4* x4 = (const float4*)x;
    const float4* w4 = (const float4*)Vw;

    // loader mapping
    const int arow = t >> 2, aseg = t & 3;              // A: 128 rows x 4 segs
    // B: 256 rows x 4 segs = 1024 units, 2 per thread

    float acc[4][4][4];
#pragma unroll
    for (int mt = 0; mt < 4; mt++)
#pragma unroll
        for (int nt = 0; nt < 4; nt++)
#pragma unroll
            for (int j = 0; j < 4; j++) acc[mt][nt][j] = 0.0f;

    // ldmatrix per-lane offsets
    const uint32_t a_lo = (uint32_t)((lane & 15) * AB_STRIDE + ((lane >> 4) << 4));
    const uint32_t b_lo = (uint32_t)(((lane & 7) + ((lane >> 4) & 1) * 8) * AB_STRIDE +
                                     (((lane >> 3) & 1) << 4));

    // ---- prologue: stage 0 ----
    {
        float4 pa0 = x4[(size_t)(r0 + arow) * 128 + aseg * 2];
        float4 pa1 = x4[(size_t)(r0 + arow) * 128 + aseg * 2 + 1];
        uint32_t ad = sb + SM_A + (uint32_t)(arow * AB_STRIDE + aseg * 16);
        STS128(ad, pack2(pa0.x, pa0.y), pack2(pa0.z, pa0.w),
                   pack2(pa1.x, pa1.y), pack2(pa1.z, pa1.w));
#pragma unroll
        for (int i = 0; i < 2; i++) {
            int u = t + i * 512, br = u >> 2, bs = u & 3;
            float4 pb0 = w4[(size_t)br * 128 + bs * 2];
            float4 pb1 = w4[(size_t)br * 128 + bs * 2 + 1];
            uint32_t bd = sb + SM_B + (uint32_t)(br * AB_STRIDE + bs * 16);
            STS128(bd, pack2(pb0.x, pb0.y), pack2(pb0.z, pb0.w),
                       pack2(pb1.x, pb1.y), pack2(pb1.z, pb1.w));
        }
    }
    __syncthreads();

    for (int s = 0; s < STAGES; s++) {
        // prefetch stage s+1 (LDG only; STS after compute)
        float4 pa0, pa1, pb0, pb1, pb2, pb3;
        if (s + 1 < STAGES) {
            const int c0 = (s + 1) * 8;
            pa0 = x4[(size_t)(r0 + arow) * 128 + c0 + aseg * 2];
            pa1 = x4[(size_t)(r0 + arow) * 128 + c0 + aseg * 2 + 1];
            int u0 = t, br0 = u0 >> 2, bs0 = u0 & 3;
            int u1 = t + 512, br1 = u1 >> 2, bs1 = u1 & 3;
            pb0 = w4[(size_t)br0 * 128 + c0 + bs0 * 2];
            pb1 = w4[(size_t)br0 * 128 + c0 + bs0 * 2 + 1];
            pb2 = w4[(size_t)br1 * 128 + c0 + bs1 * 2];
            pb3 = w4[(size_t)br1 * 128 + c0 + bs1 * 2 + 1];
        }

        // ---- compute stage s ----
        const uint32_t ab = sb + SM_A + (uint32_t)(s * A_SLICE);
        const uint32_t bb = sb + SM_B + (uint32_t)((s & 1) * B_BUF);
#pragma unroll
        for (int k16 = 0; k16 < 2; k16++) {
            const uint32_t kof = (uint32_t)(k16 * 32);
            uint32_t af[4][4];
#pragma unroll
            for (int mt = 0; mt < 4; mt++)
                LDM_X4(af[mt][0], af[mt][1], af[mt][2], af[mt][3],
                       ab + (uint32_t)((wm * 64 + mt * 16) * AB_STRIDE) + kof + a_lo);
            uint32_t bf[4][2];
#pragma unroll
            for (int pr = 0; pr < 2; pr++) {
                uint32_t f0, f1, f2, f3;
                LDM_X4(f0, f1, f2, f3,
                       bb + (uint32_t)((wn * 32 + pr * 16) * AB_STRIDE) + kof + b_lo);
                bf[2 * pr][0] = f0; bf[2 * pr][1] = f1;
                bf[2 * pr + 1][0] = f2; bf[2 * pr + 1][1] = f3;
            }
#pragma unroll
            for (int mt = 0; mt < 4; mt++)
#pragma unroll
                for (int nt = 0; nt < 4; nt++)
                    mma_f16(acc[mt][nt], af[mt], bf[nt]);
        }

        // ---- cvt + STS stage s+1 ----
        if (s + 1 < STAGES) {
            uint32_t ad = sb + SM_A + (uint32_t)((s + 1) * A_SLICE + arow * AB_STRIDE + aseg * 16);
            STS128(ad, pack2(pa0.x, pa0.y), pack2(pa0.z, pa0.w),
                       pack2(pa1.x, pa1.y), pack2(pa1.z, pa1.w));
            uint32_t bbn = sb + SM_B + (uint32_t)(((s + 1) & 1) * B_BUF);
            int u0 = t, br0 = u0 >> 2, bs0 = u0 & 3;
            int u1 = t + 512, br1 = u1 >> 2, bs1 = u1 & 3;
            STS128(bbn + (uint32_t)(br0 * AB_STRIDE + bs0 * 16),
                   pack2(pb0.x, pb0.y), pack2(pb0.z, pb0.w),
                   pack2(pb1.x, pb1.y), pack2(pb1.z, pb1.w));
            STS128(bbn + (uint32_t)(br1 * AB_STRIDE + bs1 * 16),
                   pack2(pb2.x, pb2.y), pack2(pb2.z, pb2.w),
                   pack2(pb3.x, pb3.y), pack2(pb3.z, pb3.w));
        }
        __syncthreads();
    }

    // ---------------- epilogue: scores ----------------
    if (t < 128) s_red[t] = 0.0f;
    __syncthreads();

    float vb[4][2], wv[4][2];
#pragma unroll
    for (int nt = 0; nt < 4; nt++)
#pragma unroll
        for (int j = 0; j < 2; j++) {
            int c = wn * 32 + nt * 8 + 2 * rr + j;
            vb[nt][j] = Vb[c];
            wv[nt][j] = ww[c];
        }

#pragma unroll
    for (int mt = 0; mt < 4; mt++) {
        float plo = 0.0f, phi = 0.0f;
#pragma unroll
        for (int nt = 0; nt < 4; nt++)
#pragma unroll
            for (int j = 0; j < 2; j++) {
                float tlo, thi;
                asm("tanh.approx.f32 %0, %1;" : "=f"(tlo) : "f"(acc[mt][nt][j] + vb[nt][j]));
                asm("tanh.approx.f32 %0, %1;" : "=f"(thi) : "f"(acc[mt][nt][j + 2] + vb[nt][j]));
                plo = fmaf(tlo, wv[nt][j], plo);
                phi = fmaf(thi, wv[nt][j], phi);
            }
        plo += __shfl_xor_sync(0xFFFFFFFFu, plo, 1);
        plo += __shfl_xor_sync(0xFFFFFFFFu, plo, 2);
        phi += __shfl_xor_sync(0xFFFFFFFFu, phi, 1);
        phi += __shfl_xor_sync(0xFFFFFFFFu, phi, 2);
        if (rr == 0) {
            int row = wm * 64 + mt * 16 + q;
            atomicAdd(&s_red[row], plo);
            atomicAdd(&s_red[row + 8], phi);
        }
    }
    __syncthreads();

    if (t < 128) {
        int r = r0 + t;
        int b = bidx[r];
        float al = expf(s_red[t] + wb[0]);
        s_alpha[t] = al;
        s_bag[t]   = b;
        atomicAdd(&g_sum_alpha[b], al);
    }
    __syncthreads();

    // ---------------- fused pooling (k2 eliminated) ----------------
    // thread t owns column e = t; x tile is resident as fp16 in smem.
    {
        const __half* hp = (const __half*)(smem + (t >> 5) * A_SLICE + (t & 31) * 2);
        float accp = 0.0f;
        int cur = s_bag[0];
#pragma unroll 4
        for (int r = 0; r < 128; r++) {
            int b = s_bag[r];
            if (b != cur) {
                atomicAdd(&g_bag_sum[(size_t)cur * E_DIM + t], accp);
                accp = 0.0f;
                cur = b;
            }
            accp = fmaf(s_alpha[r], __half2float(hp[r * (AB_STRIDE / 2)]), accp);
        }
        atomicAdd(&g_bag_sum[(size_t)cur * E_DIM + t], accp);
    }
}

// ---------------------------------------------------------------------------
// K3: logits + 2-way softmax (one warp per bag), divide by sum_alpha here
// ---------------------------------------------------------------------------
__global__ __launch_bounds__(256)
void k3_logits(const float* __restrict__ dw, const float* __restrict__ db,
               float* __restrict__ out)
{
    int warp = (blockIdx.x * blockDim.x + threadIdx.x) >> 5;
    int lane = threadIdx.x & 31;
    if (warp >= B_BAGS) return;

    float s0 = 0.0f, s1 = 0.0f;
    for (int e = lane; e < E_DIM; e += 32) {
        float bs = g_bag_sum[(size_t)warp * E_DIM + e];
        s0 = fmaf(bs, dw[e], s0);
        s1 = fmaf(bs, dw[E_DIM + e], s1);
    }
#pragma unroll
    for (int off = 16; off > 0; off >>= 1) {
        s0 += __shfl_xor_sync(0xFFFFFFFFu, s0, off);
        s1 += __shfl_xor_sync(0xFFFFFFFFu, s1, off);
    }
    if (lane == 0) {
        float inv = 1.0f / g_sum_alpha[warp];
        float l0 = fmaf(s0, inv, db[0]);
        float l1 = fmaf(s1, inv, db[1]);
        float m = fmaxf(l0, l1);
        float e0 = expf(l0 - m), e1 = expf(l1 - m);
        float d = e0 + e1;
        out[warp * 2 + 0] = e0 / d;
        out[warp * 2 + 1] = e1 / d;
    }
}

// ---------------------------------------------------------------------------
extern "C" void kernel_launch(void* const* d_in, const int* in_sizes, int n_in,
                              void* d_out, int out_size)
{
    const float* x    = (const float*)d_in[0];
    const float* Vw   = (const float*)d_in[1];
    const float* Vb   = (const float*)d_in[2];
    const float* ww   = (const float*)d_in[3];
    const float* wb   = (const float*)d_in[4];
    const float* dw   = (const float*)d_in[5];
    const float* db   = (const float*)d_in[6];
    const int*   bidx = (const int*)d_in[7];
    float* out = (float*)d_out;

    static int smem_set = 0;
    if (!smem_set) {
        cudaFuncSetAttribute(k1_score, cudaFuncAttributeMaxDynamicSharedMemorySize, SM_TOTAL);
        smem_set = 1;
    }

    k0_zero<<<(B_BAGS * E_DIM + 255) / 256, 256>>>();
    k1_score<<<N_TOT / 128, 512, SM_TOTAL>>>(x, Vw, Vb, ww, wb, bidx);
    k3_logits<<<(B_BAGS * 32 + 255) / 256, 256>>>(dw, db, out);
}

// round 8
// speedup vs baseline: 5.4617x; 1.2890x over previous
#include <cuda_runtime.h>
#include <cuda_fp16.h>
#include <cstdint>
#include <math.h>

#define N_TOT 262144
#define E_DIM 512
#define H_DIM 256
#define B_BAGS 512

// Scratch (allocation-free rule: __device__ globals)
__device__ float g_sum_alpha[B_BAGS];
__device__ float g_bag_sum[B_BAGS * E_DIM];
__device__ __half g_wh[H_DIM * E_DIM];   // Vw pre-converted to fp16 (256 KB)

// ============================================================================
// helpers
// ============================================================================
__device__ __forceinline__ uint32_t smem_to_u32(const void* p) {
    uint32_t a;
    asm("{ .reg .u64 t; cvta.to.shared.u64 t, %1; cvt.u32.u64 %0, t; }" : "=r"(a) : "l"(p));
    return a;
}
#define LDM_X4(r0_, r1_, r2_, r3_, addr) \
    asm volatile("ldmatrix.sync.aligned.m8n8.x4.shared.b16 {%0,%1,%2,%3}, [%4];" \
                 : "=r"(r0_), "=r"(r1_), "=r"(r2_), "=r"(r3_) : "r"(addr))
#define STS128(addr, a, b, c, d) \
    asm volatile("st.shared.v4.b32 [%0], {%1,%2,%3,%4};" \
                 :: "r"(addr), "r"(a), "r"(b), "r"(c), "r"(d) : "memory")
#define CP_ASYNC16(dst_u32, src_ptr) \
    asm volatile("cp.async.cg.shared.global [%0], [%1], 16;" :: "r"(dst_u32), "l"(src_ptr))
#define CP_COMMIT() asm volatile("cp.async.commit_group;" ::: "memory")
#define CP_WAIT(n)  asm volatile("cp.async.wait_group %0;" :: "n"(n) : "memory")

__device__ __forceinline__ void mma_f16(float* c, const uint32_t* a, const uint32_t* b) {
    asm volatile(
        "mma.sync.aligned.m16n8k16.row.col.f32.f16.f16.f32 "
        "{%0,%1,%2,%3}, {%4,%5,%6,%7}, {%8,%9}, {%0,%1,%2,%3};"
        : "+f"(c[0]), "+f"(c[1]), "+f"(c[2]), "+f"(c[3])
        : "r"(a[0]), "r"(a[1]), "r"(a[2]), "r"(a[3]), "r"(b[0]), "r"(b[1]));
}
__device__ __forceinline__ uint32_t pack2(float lo, float hi) {
    __half2 h = __floats2half2_rn(lo, hi);
    return *reinterpret_cast<uint32_t*>(&h);
}

// ============================================================================
// K1 geometry: CTA = 128(M) x 256(H) x K512 fp16 mma, k-chunk 32 (16 stages).
// A tile fully resident (16 slices, register-staged cvt). B: cp.async fp16,
// triple-buffered, 2-stage lookahead. Row stride 80B (conflict-free ldmatrix).
// ============================================================================
#define STAGES 16
#define AB_STRIDE 80
#define A_SLICE (128 * AB_STRIDE)        // 10240
#define SM_A 0
#define SM_B (STAGES * A_SLICE)          // 163840
#define B_BUF (256 * AB_STRIDE)          // 20480
#define SM_TOTAL (SM_B + 3 * B_BUF)      // 225280

__global__ void k0_zero() {
    int i = blockIdx.x * blockDim.x + threadIdx.x;
    if (i < B_BAGS * E_DIM) g_bag_sum[i] = 0.0f;
    if (i < B_BAGS) g_sum_alpha[i] = 0.0f;
}

// Vw fp32 -> fp16 (one shot per launch, ~3us)
__global__ void kconv(const float* __restrict__ Vw) {
    int i = blockIdx.x * blockDim.x + threadIdx.x;   // 16384 threads x 8 halves
    const float4* src = (const float4*)Vw;
    float4 a = src[i * 2], b = src[i * 2 + 1];
    uint32_t p[4] = {pack2(a.x, a.y), pack2(a.z, a.w), pack2(b.x, b.y), pack2(b.z, b.w)};
    *(uint4*)(g_wh + (size_t)i * 8) = *(uint4*)p;
}

__device__ __forceinline__ void issue_B(uint32_t sb, int s, int t) {
    const uint32_t bbase = sb + SM_B + (uint32_t)((s % 3) * B_BUF);
#pragma unroll
    for (int i = 0; i < 2; i++) {
        int u = t + i * 512;                // 0..1023 : 256 rows x 4 segs
        int br = u >> 2, seg = u & 3;
        CP_ASYNC16(bbase + (uint32_t)(br * AB_STRIDE + seg * 16),
                   (const void*)(g_wh + (size_t)br * E_DIM + s * 32 + seg * 8));
    }
    CP_COMMIT();
}

__global__ __launch_bounds__(512, 1)
void k1_score(const float* __restrict__ x,    // [N, E]
              const float* __restrict__ Vb,   // [H]
              const float* __restrict__ ww,   // [1, H]
              const float* __restrict__ wb,   // [1]
              const int*   __restrict__ bidx) // [N]
{
    extern __shared__ char smem[];
    __shared__ float s_red[128];
    __shared__ float s_alpha[128];
    __shared__ int   s_bag[128];

    const uint32_t sb = smem_to_u32(smem);
    const int t    = threadIdx.x;
    const int wid  = t >> 5;
    const int lane = t & 31;
    const int q    = lane >> 2;
    const int rr   = lane & 3;
    const int wm   = wid >> 3;      // 0..1 : rows [wm*64, +64)
    const int wn   = wid & 7;       // 0..7 : cols [wn*32, +32)
    const int r0   = blockIdx.x * 128;

    const float4* x4 = (const float4*)x;
    const int arow = t >> 2, aseg = t & 3;   // A: 128 rows x 4 x 16B(fp16)

    float acc[4][4][4];
#pragma unroll
    for (int mt = 0; mt < 4; mt++)
#pragma unroll
        for (int nt = 0; nt < 4; nt++)
#pragma unroll
            for (int j = 0; j < 4; j++) acc[mt][nt][j] = 0.0f;

    const uint32_t a_lo = (uint32_t)((lane & 15) * AB_STRIDE + ((lane >> 4) << 4));
    const uint32_t b_lo = (uint32_t)(((lane & 7) + ((lane >> 4) & 1) * 8) * AB_STRIDE +
                                     (((lane >> 3) & 1) << 4));

    // ---- prologue ----
    issue_B(sb, 0, t);
    issue_B(sb, 1, t);
    issue_B(sb, 2, t);
    float4 ha0, ha1;
    {   // A stage 0: LDG -> STS now; A stage 1: LDG, hold in regs
        ha0 = x4[(size_t)(r0 + arow) * 128 + 0 * 8 + aseg * 2];
        ha1 = x4[(size_t)(r0 + arow) * 128 + 0 * 8 + aseg * 2 + 1];
        uint32_t ad = sb + SM_A + (uint32_t)(0 * A_SLICE + arow * AB_STRIDE + aseg * 16);
        STS128(ad, pack2(ha0.x, ha0.y), pack2(ha0.z, ha0.w),
                   pack2(ha1.x, ha1.y), pack2(ha1.z, ha1.w));
        ha0 = x4[(size_t)(r0 + arow) * 128 + 1 * 8 + aseg * 2];
        ha1 = x4[(size_t)(r0 + arow) * 128 + 1 * 8 + aseg * 2 + 1];
    }

    for (int s = 0; s < STAGES; s++) {
        CP_WAIT(2);                          // B stage s landed
        if (s + 1 < STAGES) {                // STS A s+1 from held regs
            uint32_t ad = sb + SM_A + (uint32_t)((s + 1) * A_SLICE + arow * AB_STRIDE + aseg * 16);
            STS128(ad, pack2(ha0.x, ha0.y), pack2(ha0.z, ha0.w),
                       pack2(ha1.x, ha1.y), pack2(ha1.z, ha1.w));
        }
        __syncthreads();                     // A s+1 + B s visible to all
        if (s + 2 < STAGES) {                // LDG A s+2 (in flight across compute)
            ha0 = x4[(size_t)(r0 + arow) * 128 + (s + 2) * 8 + aseg * 2];
            ha1 = x4[(size_t)(r0 + arow) * 128 + (s + 2) * 8 + aseg * 2 + 1];
        }

        // ---- compute stage s ----
        const uint32_t ab = sb + SM_A + (uint32_t)(s * A_SLICE);
        const uint32_t bb = sb + SM_B + (uint32_t)((s % 3) * B_BUF);
#pragma unroll
        for (int k16 = 0; k16 < 2; k16++) {
            const uint32_t kof = (uint32_t)(k16 * 32);
            uint32_t af[4][4];
#pragma unroll
            for (int mt = 0; mt < 4; mt++)
                LDM_X4(af[mt][0], af[mt][1], af[mt][2], af[mt][3],
                       ab + (uint32_t)((wm * 64 + mt * 16) * AB_STRIDE) + kof + a_lo);
            uint32_t bf[4][2];
#pragma unroll
            for (int pr = 0; pr < 2; pr++) {
                uint32_t f0, f1, f2, f3;
                LDM_X4(f0, f1, f2, f3,
                       bb + (uint32_t)((wn * 32 + pr * 16) * AB_STRIDE) + kof + b_lo);
                bf[2 * pr][0] = f0; bf[2 * pr][1] = f1;
                bf[2 * pr + 1][0] = f2; bf[2 * pr + 1][1] = f3;
            }
#pragma unroll
            for (int mt = 0; mt < 4; mt++)
#pragma unroll
                for (int nt = 0; nt < 4; nt++)
                    mma_f16(acc[mt][nt], af[mt], bf[nt]);
        }
        __syncthreads();                     // all warps done with B buf s%3
        if (s + 3 < STAGES) issue_B(sb, s + 3, t);   // refill buf s%3
    }

    // ---------------- epilogue: scores ----------------
    if (t < 128) s_red[t] = 0.0f;
    __syncthreads();

    float vb[4][2], wv[4][2];
#pragma unroll
    for (int nt = 0; nt < 4; nt++)
#pragma unroll
        for (int j = 0; j < 2; j++) {
            int c = wn * 32 + nt * 8 + 2 * rr + j;
            vb[nt][j] = Vb[c];
            wv[nt][j] = ww[c];
        }

#pragma unroll
    for (int mt = 0; mt < 4; mt++) {
        float plo = 0.0f, phi = 0.0f;
#pragma unroll
        for (int nt = 0; nt < 4; nt++)
#pragma unroll
            for (int j = 0; j < 2; j++) {
                float tlo, thi;
                asm("tanh.approx.f32 %0, %1;" : "=f"(tlo) : "f"(acc[mt][nt][j] + vb[nt][j]));
                asm("tanh.approx.f32 %0, %1;" : "=f"(thi) : "f"(acc[mt][nt][j + 2] + vb[nt][j]));
                plo = fmaf(tlo, wv[nt][j], plo);
                phi = fmaf(thi, wv[nt][j], phi);
            }
        plo += __shfl_xor_sync(0xFFFFFFFFu, plo, 1);
        plo += __shfl_xor_sync(0xFFFFFFFFu, plo, 2);
        phi += __shfl_xor_sync(0xFFFFFFFFu, phi, 1);
        phi += __shfl_xor_sync(0xFFFFFFFFu, phi, 2);
        if (rr == 0) {
            int row = wm * 64 + mt * 16 + q;
            atomicAdd(&s_red[row], plo);
            atomicAdd(&s_red[row + 8], phi);
        }
    }
    __syncthreads();

    if (t < 128) {
        int r = r0 + t;
        int b = bidx[r];
        float al = expf(s_red[t] + wb[0]);
        s_alpha[t] = al;
        s_bag[t]   = b;
        atomicAdd(&g_sum_alpha[b], al);
    }
    __syncthreads();

    // ---------------- fused pooling (x tile resident as fp16) ----------------
    {
        const __half* hp = (const __half*)(smem + (t >> 5) * A_SLICE + (t & 31) * 2);
        float accp = 0.0f;
        int cur = s_bag[0];
#pragma unroll 4
        for (int r = 0; r < 128; r++) {
            int b = s_bag[r];
            if (b != cur) {
                atomicAdd(&g_bag_sum[(size_t)cur * E_DIM + t], accp);
                accp = 0.0f;
                cur = b;
            }
            accp = fmaf(s_alpha[r], __half2float(hp[r * (AB_STRIDE / 2)]), accp);
        }
        atomicAdd(&g_bag_sum[(size_t)cur * E_DIM + t], accp);
    }
}

// ---------------------------------------------------------------------------
// K3: logits + 2-way softmax (one warp per bag), divide by sum_alpha here
// ---------------------------------------------------------------------------
__global__ __launch_bounds__(256)
void k3_logits(const float* __restrict__ dw, const float* __restrict__ db,
               float* __restrict__ out)
{
    int warp = (blockIdx.x * blockDim.x + threadIdx.x) >> 5;
    int lane = threadIdx.x & 31;
    if (warp >= B_BAGS) return;

    float s0 = 0.0f, s1 = 0.0f;
    for (int e = lane; e < E_DIM; e += 32) {
        float bs = g_bag_sum[(size_t)warp * E_DIM + e];
        s0 = fmaf(bs, dw[e], s0);
        s1 = fmaf(bs, dw[E_DIM + e], s1);
    }
#pragma unroll
    for (int off = 16; off > 0; off >>= 1) {
        s0 += __shfl_xor_sync(0xFFFFFFFFu, s0, off);
        s1 += __shfl_xor_sync(0xFFFFFFFFu, s1, off);
    }
    if (lane == 0) {
        float inv = 1.0f / g_sum_alpha[warp];
        float l0 = fmaf(s0, inv, db[0]);
        float l1 = fmaf(s1, inv, db[1]);
        float m = fmaxf(l0, l1);
        float e0 = expf(l0 - m), e1 = expf(l1 - m);
        float d = e0 + e1;
        out[warp * 2 + 0] = e0 / d;
        out[warp * 2 + 1] = e1 / d;
    }
}

// ---------------------------------------------------------------------------
extern "C" void kernel_launch(void* const* d_in, const int* in_sizes, int n_in,
                              void* d_out, int out_size)
{
    const float* x    = (const float*)d_in[0];
    const float* Vw   = (const float*)d_in[1];
    const float* Vb   = (const float*)d_in[2];
    const float* ww   = (const float*)d_in[3];
    const float* wb   = (const float*)d_in[4];
    const float* dw   = (const float*)d_in[5];
    const float* db   = (const float*)d_in[6];
    const int*   bidx = (const int*)d_in[7];
    float* out = (float*)d_out;

    static int smem_set = 0;
    if (!smem_set) {
        cudaFuncSetAttribute(k1_score, cudaFuncAttributeMaxDynamicSharedMemorySize, SM_TOTAL);
        smem_set = 1;
    }

    k0_zero<<<(B_BAGS * E_DIM + 255) / 256, 256>>>();
    kconv<<<(H_DIM * E_DIM / 8 + 255) / 256, 256>>>(Vw);
    k1_score<<<N_TOT / 128, 512, SM_TOTAL>>>(x, Vb, ww, wb, bidx);
    k3_logits<<<(B_BAGS * 32 + 255) / 256, 256>>>(dw, db, out);
}